// round 16
// baseline (speedup 1.0000x reference)
#include <cuda_runtime.h>
#include <cuda_bf16.h>
#include <cuda_fp16.h>
#include <math.h>

#define MAXN 50000
#define MAXE 800000
#define MAXL 1600000

// -------- scratch (device globals: allocation-free contract) --------
__device__ float  g_px[(size_t)MAXN * 128];
__device__ __half g_fused[(size_t)MAXE * 128];
__device__ __half g_h[(size_t)MAXE * 128];
// line-graph CSR (edge <- line edges)
__device__ int    g_lcnt[MAXE];
__device__ int    g_cur[MAXE];
__device__ int    g_off[MAXE + 1];
__device__ int    g_csr[MAXL];
__device__ int    g_bsum[1024];
// node CSR (node <- edges by dst)
__device__ int    g_ncntI[MAXN];
__device__ int    g_ncur[MAXN];
__device__ int    g_noff[MAXN + 1];
__device__ int    g_ncsr[MAXE];
__device__ int    g_bsum2[1024];
// BN
__device__ float  g_bnsum[128];
__device__ float  g_bnsumsq[128];
__device__ float  g_scale[128];
__device__ float  g_shift[128];
// pre-split weights (bf16 hi/lo)
__device__ __nv_bfloat16 g_Wph[128 * 256];
__device__ __nv_bfloat16 g_Wpl[128 * 256];
__device__ __nv_bfloat16 g_W1h[128 * 128];
__device__ __nv_bfloat16 g_W1l[128 * 128];

// ====================================================================
__device__ __forceinline__ void mma_bf16(float* c, const unsigned* a,
                                         unsigned b0, unsigned b1) {
    asm volatile(
        "mma.sync.aligned.m16n8k16.row.col.f32.bf16.bf16.f32 "
        "{%0,%1,%2,%3}, {%4,%5,%6,%7}, {%8,%9}, {%0,%1,%2,%3};"
        : "+f"(c[0]), "+f"(c[1]), "+f"(c[2]), "+f"(c[3])
        : "r"(a[0]), "r"(a[1]), "r"(a[2]), "r"(a[3]), "r"(b0), "r"(b1));
}

__device__ __forceinline__ void redg_f32(float* p, float v) {
    asm volatile("red.global.add.f32 [%0], %1;" :: "l"(p), "f"(v) : "memory");
}

__global__ void k_split(const float* __restrict__ W, __nv_bfloat16* __restrict__ Wh,
                        __nv_bfloat16* __restrict__ Wl, int n) {
    int i = blockIdx.x * blockDim.x + threadIdx.x;
    if (i >= n) return;
    float v = W[i];
    __nv_bfloat16 h = __float2bfloat16_rn(v);
    Wh[i] = h;
    Wl[i] = __float2bfloat16_rn(v - __bfloat162float(h));
}

#define SMS  40   // per-kb stage row stride (bf16 elems)
#define AFS 136   // full-K A row stride: 272B -> 4-bank shift per row
#define ICAP 5120 // smem csr-slice capacity (ints)

template <int EPI>
__global__ __launch_bounds__(256, 2) void k_gemm(
    const float* __restrict__ A,
    const __nv_bfloat16* __restrict__ Wh, const __nv_bfloat16* __restrict__ Wl,
    const float* __restrict__ bias, const float* __restrict__ prelu_a,
    float* __restrict__ Cf, __half* __restrict__ Ch, int M, int K) {
    extern __shared__ char smem_raw[];
    __nv_bfloat16* Ahi = (__nv_bfloat16*)smem_raw;
    const int a_stride = (EPI == 1) ? AFS : SMS;
    __nv_bfloat16* Alo = Ahi + 128 * a_stride;
    __nv_bfloat16* Bh  = Alo + 128 * a_stride;
    __nv_bfloat16* Bl  = Bh + 128 * SMS;
    __shared__ int s_off[129];

    const int tid = threadIdx.x;
    const int lane = tid & 31;
    const int wid = tid >> 5;
    const int g = lane >> 2;
    const int t = lane & 3;
    const int warp_m = wid & 3;
    const int warp_n = wid >> 2;
    const int row0 = blockIdx.x * 128;

    const int ld_row = tid >> 1;
    const int ld_k = (tid & 1) * 16;

    // ---------------- EPI==1 prologue: CSR gather-mean into smem ----------------
    if (EPI == 1) {
        for (int i = tid; i < 129; i += 256)
            s_off[i] = g_off[min(row0 + i, M)];
        __syncthreads();
        const int base = s_off[0];
        const int total = s_off[128] - base;
        int* s_idx = (int*)Bh;
        const int n_sm = min(total, ICAP);
        for (int i = tid; i < n_sm; i += 256)
            s_idx[i] = g_csr[base + i];
        __syncthreads();

        const int gr = tid >> 4;
        const int gc = (tid & 15) * 8;
#pragma unroll
        for (int w = 0; w < 8; w++) {
            int r = w * 16 + gr;
            int st = s_off[r] - base;
            int en = s_off[r + 1] - base;
            float s[8];
#pragma unroll
            for (int j = 0; j < 8; j++) s[j] = 0.f;
            for (int i = st; i < en; i++) {
                int se = (i < n_sm) ? s_idx[i] : g_csr[base + i];
                float4 raw = *(const float4*)&g_fused[(size_t)se * 128 + gc];
                unsigned u0 = __float_as_uint(raw.x), u1 = __float_as_uint(raw.y);
                unsigned u2 = __float_as_uint(raw.z), u3 = __float_as_uint(raw.w);
                float2 v0 = __half22float2(*(__half2*)&u0);
                float2 v1 = __half22float2(*(__half2*)&u1);
                float2 v2 = __half22float2(*(__half2*)&u2);
                float2 v3 = __half22float2(*(__half2*)&u3);
                s[0] += v0.x; s[1] += v0.y; s[2] += v1.x; s[3] += v1.y;
                s[4] += v2.x; s[5] += v2.y; s[6] += v3.x; s[7] += v3.y;
            }
            float inv = 1.f / (float)max(en - st, 1);
            __nv_bfloat16 hi[8], lo[8];
#pragma unroll
            for (int j = 0; j < 8; j++) {
                float sv = s[j] * inv;
                hi[j] = __float2bfloat16_rn(sv);
                lo[j] = __float2bfloat16_rn(sv - __bfloat162float(hi[j]));
            }
            *(uint4*)&Ahi[r * AFS + gc] = *(uint4*)hi;
            *(uint4*)&Alo[r * AFS + gc] = *(uint4*)lo;
        }
        __syncthreads();
    }

    float acc[2][8][4];
#pragma unroll
    for (int mt = 0; mt < 2; mt++)
#pragma unroll
        for (int nt = 0; nt < 8; nt++)
#pragma unroll
            for (int r = 0; r < 4; r++) acc[mt][nt][r] = 0.f;

    for (int kb = 0; kb < K; kb += 32) {
        if (EPI == 0) {
            int r = row0 + ld_row;
            const float* src = &A[(size_t)r * K + kb + ld_k];
#pragma unroll
            for (int j = 0; j < 4; j++) {
                float4 v = make_float4(0.f, 0.f, 0.f, 0.f);
                if (r < M) v = *(const float4*)(src + j * 4);
                float vv[4] = {v.x, v.y, v.z, v.w};
#pragma unroll
                for (int p = 0; p < 2; p++) {
                    __nv_bfloat162 hi2, lo2;
                    __nv_bfloat16 h0 = __float2bfloat16_rn(vv[2 * p]);
                    __nv_bfloat16 h1 = __float2bfloat16_rn(vv[2 * p + 1]);
                    __nv_bfloat16 l0 = __float2bfloat16_rn(vv[2 * p] - __bfloat162float(h0));
                    __nv_bfloat16 l1 = __float2bfloat16_rn(vv[2 * p + 1] - __bfloat162float(h1));
                    hi2.x = h0; hi2.y = h1; lo2.x = l0; lo2.y = l1;
                    *(__nv_bfloat162*)&Ahi[ld_row * SMS + ld_k + j * 4 + 2 * p] = hi2;
                    *(__nv_bfloat162*)&Alo[ld_row * SMS + ld_k + j * 4 + 2 * p] = lo2;
                }
            }
        }
        {
            const size_t goff = (size_t)ld_row * K + kb + ld_k;
            *(uint4*)&Bh[ld_row * SMS + ld_k] = *(const uint4*)&Wh[goff];
            *(uint4*)&Bh[ld_row * SMS + ld_k + 8] = *(const uint4*)&Wh[goff + 8];
            *(uint4*)&Bl[ld_row * SMS + ld_k] = *(const uint4*)&Wl[goff];
            *(uint4*)&Bl[ld_row * SMS + ld_k + 8] = *(const uint4*)&Wl[goff + 8];
        }
        __syncthreads();

#pragma unroll
        for (int kk = 0; kk < 32; kk += 16) {
            const int ak = (EPI == 1) ? (kb + kk) : kk;
            unsigned a_hi[2][4], a_lo[2][4];
#pragma unroll
            for (int mt = 0; mt < 2; mt++) {
                int m0 = warp_m * 32 + mt * 16 + g;
                a_hi[mt][0] = *(const unsigned*)&Ahi[m0 * a_stride + ak + 2 * t];
                a_hi[mt][1] = *(const unsigned*)&Ahi[(m0 + 8) * a_stride + ak + 2 * t];
                a_hi[mt][2] = *(const unsigned*)&Ahi[m0 * a_stride + ak + 2 * t + 8];
                a_hi[mt][3] = *(const unsigned*)&Ahi[(m0 + 8) * a_stride + ak + 2 * t + 8];
                a_lo[mt][0] = *(const unsigned*)&Alo[m0 * a_stride + ak + 2 * t];
                a_lo[mt][1] = *(const unsigned*)&Alo[(m0 + 8) * a_stride + ak + 2 * t];
                a_lo[mt][2] = *(const unsigned*)&Alo[m0 * a_stride + ak + 2 * t + 8];
                a_lo[mt][3] = *(const unsigned*)&Alo[(m0 + 8) * a_stride + ak + 2 * t + 8];
            }
#pragma unroll
            for (int nt = 0; nt < 8; nt++) {
                int n = warp_n * 64 + nt * 8 + g;
                unsigned bh0 = *(const unsigned*)&Bh[n * SMS + kk + 2 * t];
                unsigned bh1 = *(const unsigned*)&Bh[n * SMS + kk + 2 * t + 8];
                unsigned bl0 = *(const unsigned*)&Bl[n * SMS + kk + 2 * t];
                unsigned bl1 = *(const unsigned*)&Bl[n * SMS + kk + 2 * t + 8];
#pragma unroll
                for (int mt = 0; mt < 2; mt++) {
                    mma_bf16(acc[mt][nt], a_hi[mt], bh0, bh1);
                    mma_bf16(acc[mt][nt], a_hi[mt], bl0, bl1);
                    mma_bf16(acc[mt][nt], a_lo[mt], bh0, bh1);
                }
            }
        }
        __syncthreads();
    }

    // ---------------- epilogue ----------------
    float alpha = 0.f;
    if (EPI == 1) alpha = prelu_a[0];

#pragma unroll
    for (int nt = 0; nt < 8; nt++) {
        int col = warp_n * 64 + nt * 8 + 2 * t;
        float b0 = 0.f, b1 = 0.f;
        if (EPI == 1) { b0 = bias[col]; b1 = bias[col + 1]; }
        float s0 = 0.f, s1 = 0.f, q0 = 0.f, q1 = 0.f;
#pragma unroll
        for (int mt = 0; mt < 2; mt++) {
            int r0 = row0 + warp_m * 32 + mt * 16 + g;
            int r1 = r0 + 8;
            float v0 = acc[mt][nt][0], v1 = acc[mt][nt][1];
            float v2 = acc[mt][nt][2], v3 = acc[mt][nt][3];
            if (EPI == 1) {
                v0 += b0; v1 += b1; v2 += b0; v3 += b1;
                v0 = (v0 >= 0.f) ? v0 : alpha * v0;
                v1 = (v1 >= 0.f) ? v1 : alpha * v1;
                v2 = (v2 >= 0.f) ? v2 : alpha * v2;
                v3 = (v3 >= 0.f) ? v3 : alpha * v3;
                if (r0 < M) {
                    *(__half2*)&Ch[(size_t)r0 * 128 + col] = __floats2half2_rn(v0, v1);
                    s0 += v0; s1 += v1; q0 += v0 * v0; q1 += v1 * v1;
                }
                if (r1 < M) {
                    *(__half2*)&Ch[(size_t)r1 * 128 + col] = __floats2half2_rn(v2, v3);
                    s0 += v2; s1 += v3; q0 += v2 * v2; q1 += v3 * v3;
                }
            } else {
                if (r0 < M) *(float2*)&Cf[(size_t)r0 * 128 + col] = make_float2(v0, v1);
                if (r1 < M) *(float2*)&Cf[(size_t)r1 * 128 + col] = make_float2(v2, v3);
            }
        }
        if (EPI == 1) {
#pragma unroll
            for (int m = 4; m <= 16; m <<= 1) {
                s0 += __shfl_xor_sync(0xffffffffu, s0, m);
                s1 += __shfl_xor_sync(0xffffffffu, s1, m);
                q0 += __shfl_xor_sync(0xffffffffu, q0, m);
                q1 += __shfl_xor_sync(0xffffffffu, q1, m);
            }
            if (g == 0) {
                redg_f32(&g_bnsum[col], s0);
                redg_f32(&g_bnsum[col + 1], s1);
                redg_f32(&g_bnsumsq[col], q0);
                redg_f32(&g_bnsumsq[col + 1], q1);
            }
        }
    }
}

// ====================================================================
// K2: fused = edge_attr + 0.5*(px[src]+px[dst]) (fp16, STG.64)
// ====================================================================
__global__ void k_fuse(const float* __restrict__ ea, const int* __restrict__ ei,
                       int E) {
    int tt = blockIdx.x * blockDim.x + threadIdx.x;
    int e = tt >> 5;
    int lane = tt & 31;
    if (e >= E) return;
    int s = ei[e];
    int d = ei[E + e];
    int c = lane * 4;
    float4 a = *(const float4*)&ea[(size_t)e * 128 + c];
    float4 ps = *(const float4*)&g_px[(size_t)s * 128 + c];
    float4 pd = *(const float4*)&g_px[(size_t)d * 128 + c];
    __half2 h01 = __floats2half2_rn(a.x + 0.5f * (ps.x + pd.x),
                                    a.y + 0.5f * (ps.y + pd.y));
    __half2 h23 = __floats2half2_rn(a.z + 0.5f * (ps.z + pd.z),
                                    a.w + 0.5f * (ps.w + pd.w));
    float2 pk;
    pk.x = __uint_as_float(*(unsigned*)&h01);
    pk.y = __uint_as_float(*(unsigned*)&h23);
    *(float2*)&g_fused[(size_t)e * 128 + c] = pk;
}

// ---------------- generic CSR build: count -> scan -> fill ----------------
__global__ void k_cnt(const int* __restrict__ dst, int* __restrict__ cnt, int n) {
    int tt = blockIdx.x * blockDim.x + threadIdx.x;
    if (tt < n) atomicAdd(&cnt[dst[tt]], 1);
}

__global__ void k_scan1p(const int* __restrict__ cnt, int* __restrict__ off,
                         int* __restrict__ bsum, int n) {
    __shared__ int s[256];
    int tid = threadIdx.x;
    int base = blockIdx.x * 1024 + tid * 4;
    int v[4], p[4];
    int tot = 0;
#pragma unroll
    for (int j = 0; j < 4; j++) {
        v[j] = (base + j < n) ? cnt[base + j] : 0;
        p[j] = tot;
        tot += v[j];
    }
    s[tid] = tot;
    __syncthreads();
    for (int d = 1; d < 256; d <<= 1) {
        int tmp = (tid >= d) ? s[tid - d] : 0;
        __syncthreads();
        s[tid] += tmp;
        __syncthreads();
    }
    int excl = s[tid] - tot;
#pragma unroll
    for (int j = 0; j < 4; j++)
        if (base + j < n) off[base + j] = excl + p[j];
    if (tid == 255) bsum[blockIdx.x] = s[255];
}

__global__ void k_scan2p(int* __restrict__ bsum, int* __restrict__ off,
                         int nb, int n, int total) {
    __shared__ int s[1024];
    int tid = threadIdx.x;
    int v = (tid < nb) ? bsum[tid] : 0;
    s[tid] = v;
    __syncthreads();
    for (int d = 1; d < 1024; d <<= 1) {
        int tmp = (tid >= d) ? s[tid - d] : 0;
        __syncthreads();
        s[tid] += tmp;
        __syncthreads();
    }
    if (tid < nb) bsum[tid] = s[tid] - v;
    if (tid == 0) off[n] = total;
}

__global__ void k_scan3p(int* __restrict__ off, const int* __restrict__ bsum,
                         int n) {
    int i = blockIdx.x * blockDim.x + threadIdx.x;
    if (i < n) off[i] += bsum[i >> 10];
}

// fill line-graph csr: csr[pos] = src line edge
__global__ void k_fill(const int* __restrict__ lei, int L) {
    int l = blockIdx.x * blockDim.x + threadIdx.x;
    if (l >= L) return;
    int d = lei[L + l];
    int pos = g_off[d] + atomicAdd(&g_cur[d], 1);
    g_csr[pos] = lei[l];
}

// fill node csr: ncsr[pos] = edge id
__global__ void k_filln(const int* __restrict__ ei, int E) {
    int e = blockIdx.x * blockDim.x + threadIdx.x;
    if (e >= E) return;
    int d = ei[E + e];
    int pos = g_noff[d] + atomicAdd(&g_ncur[d], 1);
    g_ncsr[pos] = e;
}

__global__ void k_bnfin(const float* __restrict__ gamma,
                        const float* __restrict__ beta, float invE) {
    int c = threadIdx.x;
    float mean = g_bnsum[c] * invE;
    float var = g_bnsumsq[c] * invE - mean * mean;
    float sc = rsqrtf(var + 1e-5f) * gamma[c];
    g_scale[c] = sc;
    g_shift[c] = beta[c] - mean * sc;
}

// ---------------- node aggregation by gather (no atomics) ----------------
__global__ void k_out(float* __restrict__ out, int N) {
    int tt = blockIdx.x * blockDim.x + threadIdx.x;
    int n = tt >> 5;
    int lane = tt & 31;
    if (n >= N) return;
    int st = g_noff[n];
    int en = g_noff[n + 1];
    float cnt = (float)(en - st);
    int c = lane * 4;
    float f0 = 0.f, f1 = 0.f, f2 = 0.f, f3 = 0.f;
    float h0 = 0.f, h1 = 0.f, h2 = 0.f, h3 = 0.f;
    for (int i = st; i < en; i++) {
        int e = g_ncsr[i];
        float2 rf = *(const float2*)&g_fused[(size_t)e * 128 + c];
        float2 rh = *(const float2*)&g_h[(size_t)e * 128 + c];
        unsigned uf0 = __float_as_uint(rf.x), uf1 = __float_as_uint(rf.y);
        unsigned uh0 = __float_as_uint(rh.x), uh1 = __float_as_uint(rh.y);
        float2 a = __half22float2(*(__half2*)&uf0);
        float2 b = __half22float2(*(__half2*)&uf1);
        float2 p = __half22float2(*(__half2*)&uh0);
        float2 q = __half22float2(*(__half2*)&uh1);
        f0 += a.x; f1 += a.y; f2 += b.x; f3 += b.y;
        h0 += p.x; h1 += p.y; h2 += q.x; h3 += q.y;
    }
    float inv = 1.f / fmaxf(cnt, 1.f);
    float4 sc = *(const float4*)&g_scale[c];
    float4 sh = *(const float4*)&g_shift[c];
    float4 v;
    v.x = (f0 + sc.x * h0 + cnt * sh.x) * inv;
    v.y = (f1 + sc.y * h1 + cnt * sh.y) * inv;
    v.z = (f2 + sc.z * h2 + cnt * sh.z) * inv;
    v.w = (f3 + sc.w * h3 + cnt * sh.w) * inv;
    *(float4*)&out[(size_t)n * 128 + c] = v;
}

// ====================================================================
static cudaStream_t s_aux = nullptr;
static cudaEvent_t ev_fork = nullptr, ev_join = nullptr, ev_join2 = nullptr;

extern "C" void kernel_launch(void* const* d_in, const int* in_sizes, int n_in,
                              void* d_out, int out_size) {
    const float* x     = (const float*)d_in[0];
    const float* ea    = (const float*)d_in[1];
    const float* Wp    = (const float*)d_in[2];
    const float* W1    = (const float*)d_in[3];
    const float* b1    = (const float*)d_in[4];
    const float* pa    = (const float*)d_in[5];
    const float* gamma = (const float*)d_in[6];
    const float* beta  = (const float*)d_in[7];
    const int*   ei    = (const int*)d_in[8];
    const int*   lei   = (const int*)d_in[9];

    const int N = in_sizes[0] / 256;
    const int E = in_sizes[1] / 128;
    const int L = in_sizes[9] / 2;
    float* out = (float*)d_out;

    if (!s_aux) {
        cudaStreamCreateWithFlags(&s_aux, cudaStreamNonBlocking);
        cudaEventCreateWithFlags(&ev_fork, cudaEventDisableTiming);
        cudaEventCreateWithFlags(&ev_join, cudaEventDisableTiming);
        cudaEventCreateWithFlags(&ev_join2, cudaEventDisableTiming);
    }

    void *p_lcnt, *p_cur, *p_bns, *p_bnss, *p_px, *p_h;
    void *p_ncntI, *p_ncur, *p_bsum, *p_bsum2;
    void *p_Wph, *p_Wpl, *p_W1h, *p_W1l;
    cudaGetSymbolAddress(&p_lcnt, g_lcnt);
    cudaGetSymbolAddress(&p_cur, g_cur);
    cudaGetSymbolAddress(&p_bns, g_bnsum);
    cudaGetSymbolAddress(&p_bnss, g_bnsumsq);
    cudaGetSymbolAddress(&p_px, g_px);
    cudaGetSymbolAddress(&p_h, g_h);
    cudaGetSymbolAddress(&p_ncntI, g_ncntI);
    cudaGetSymbolAddress(&p_ncur, g_ncur);
    cudaGetSymbolAddress(&p_bsum, g_bsum);
    cudaGetSymbolAddress(&p_bsum2, g_bsum2);
    cudaGetSymbolAddress(&p_Wph, g_Wph);
    cudaGetSymbolAddress(&p_Wpl, g_Wpl);
    cudaGetSymbolAddress(&p_W1h, g_W1h);
    cudaGetSymbolAddress(&p_W1l, g_W1l);

    void *p_off, *p_noff;
    cudaGetSymbolAddress(&p_off, g_off);
    cudaGetSymbolAddress(&p_noff, g_noff);

    cudaMemsetAsync(p_lcnt, 0, (size_t)E * sizeof(int));
    cudaMemsetAsync(p_cur, 0, (size_t)E * sizeof(int));
    cudaMemsetAsync(p_ncntI, 0, (size_t)N * sizeof(int));
    cudaMemsetAsync(p_ncur, 0, (size_t)N * sizeof(int));
    cudaMemsetAsync(p_bns, 0, 128 * sizeof(float));
    cudaMemsetAsync(p_bnss, 0, 128 * sizeof(float));

    const int nbE = (E + 1023) / 1024;
    const int nbN = (N + 1023) / 1024;
    const int smem0 = 4 * 128 * SMS * 2;                       // 40960
    const int smem1 = 2 * 128 * AFS * 2 + 2 * 128 * SMS * 2;   // 90112

    cudaFuncSetAttribute(k_gemm<0>, cudaFuncAttributeMaxDynamicSharedMemorySize, smem0);
    cudaFuncSetAttribute(k_gemm<1>, cudaFuncAttributeMaxDynamicSharedMemorySize, smem1);

    k_split<<<(128 * 256 + 255) / 256, 256>>>(Wp, (__nv_bfloat16*)p_Wph,
                                              (__nv_bfloat16*)p_Wpl, 128 * 256);
    k_split<<<(128 * 128 + 255) / 256, 256>>>(W1, (__nv_bfloat16*)p_W1h,
                                              (__nv_bfloat16*)p_W1l, 128 * 128);

    // fork: both CSR builds on aux stream
    cudaEventRecord(ev_fork, 0);
    cudaStreamWaitEvent(s_aux, ev_fork, 0);
    // line-graph CSR (needed by gemm1)
    k_cnt<<<(L + 255) / 256, 256, 0, s_aux>>>(lei + L, (int*)p_lcnt, L);
    k_scan1p<<<nbE, 256, 0, s_aux>>>((const int*)p_lcnt, (int*)p_off, (int*)p_bsum, E);
    k_scan2p<<<1, 1024, 0, s_aux>>>((int*)p_bsum, (int*)p_off, nbE, E, L);
    k_scan3p<<<(E + 255) / 256, 256, 0, s_aux>>>((int*)p_off, (const int*)p_bsum, E);
    k_fill<<<(L + 255) / 256, 256, 0, s_aux>>>(lei, L);
    cudaEventRecord(ev_join, s_aux);
    // node CSR (needed by k_out) — continues on aux during gemm1
    k_cnt<<<(E + 255) / 256, 256, 0, s_aux>>>(ei + E, (int*)p_ncntI, E);
    k_scan1p<<<nbN, 256, 0, s_aux>>>((const int*)p_ncntI, (int*)p_noff, (int*)p_bsum2, N);
    k_scan2p<<<1, 1024, 0, s_aux>>>((int*)p_bsum2, (int*)p_noff, nbN, N, E);
    k_scan3p<<<(N + 255) / 256, 256, 0, s_aux>>>((int*)p_noff, (const int*)p_bsum2, N);
    k_filln<<<(E + 255) / 256, 256, 0, s_aux>>>(ei, E);
    cudaEventRecord(ev_join2, s_aux);

    // default stream: gemm0 -> fuse
    k_gemm<0><<<(N + 127) / 128, 256, smem0>>>(x, (const __nv_bfloat16*)p_Wph,
                                               (const __nv_bfloat16*)p_Wpl,
                                               nullptr, nullptr, (float*)p_px,
                                               nullptr, N, 256);
    k_fuse<<<(E * 32 + 255) / 256, 256>>>(ea, ei, E);

    cudaStreamWaitEvent(0, ev_join, 0);
    k_gemm<1><<<(E + 127) / 128, 256, smem1>>>(nullptr, (const __nv_bfloat16*)p_W1h,
                                               (const __nv_bfloat16*)p_W1l,
                                               b1, pa, nullptr, (__half*)p_h, E, 128);
    k_bnfin<<<1, 128>>>(gamma, beta, 1.f / (float)E);
    cudaStreamWaitEvent(0, ev_join2, 0);
    k_out<<<(N * 32 + 255) / 256, 256>>>(out, N);
}

// round 17
// speedup vs baseline: 1.3551x; 1.3551x over previous
#include <cuda_runtime.h>
#include <cuda_bf16.h>
#include <cuda_fp16.h>
#include <math.h>

#define MAXN 50000
#define MAXE 800000
#define MAXL 1600000

// -------- scratch (device globals: allocation-free contract) --------
__device__ float  g_px[(size_t)MAXN * 128];
__device__ __half g_fused[(size_t)MAXE * 128];
__device__ __half g_h[(size_t)MAXE * 128];
__device__ float  g_ncnt[MAXN];
__device__ int    g_lcnt[MAXE];
__device__ int    g_cur[MAXE];
__device__ int    g_off[MAXE + 1];
__device__ int    g_csr[MAXL];
__device__ int    g_bsum[1024];
__device__ float  g_bnsum[128];
__device__ float  g_bnsumsq[128];
__device__ float  g_scale[128];
__device__ float  g_shift[128];
// pre-split weights (fp16 hi/lo)
__device__ __half g_Wph[128 * 256];
__device__ __half g_Wpl[128 * 256];
__device__ __half g_W1h[128 * 128];
__device__ __half g_W1l[128 * 128];

// ====================================================================
// fp16 MMA: A single fp16, W = Wh + Wl (fp16 pair). 2 MMAs per fragment.
// ====================================================================
__device__ __forceinline__ void mma_f16(float* c, const unsigned* a,
                                        unsigned b0, unsigned b1) {
    asm volatile(
        "mma.sync.aligned.m16n8k16.row.col.f32.f16.f16.f32 "
        "{%0,%1,%2,%3}, {%4,%5,%6,%7}, {%8,%9}, {%0,%1,%2,%3};"
        : "+f"(c[0]), "+f"(c[1]), "+f"(c[2]), "+f"(c[3])
        : "r"(a[0]), "r"(a[1]), "r"(a[2]), "r"(a[3]), "r"(b0), "r"(b1));
}

__device__ __forceinline__ void redg_f32(float* p, float v) {
    asm volatile("red.global.add.f32 [%0], %1;" :: "l"(p), "f"(v) : "memory");
}

// split fp32 weights into fp16 hi/lo
__global__ void k_split(const float* __restrict__ W, __half* __restrict__ Wh,
                        __half* __restrict__ Wl, int n) {
    int i = blockIdx.x * blockDim.x + threadIdx.x;
    if (i >= n) return;
    float v = W[i];
    __half h = __float2half_rn(v);
    Wh[i] = h;
    Wl[i] = __float2half_rn(v - __half2float(h));
}

#define SMS  40   // per-kb stage row stride (half elems)
#define AFS 136   // full-K A row stride: 272B -> 4-bank shift per row
#define ICAP 5120 // smem csr-slice capacity (ints) = B region (20KB)

template <int EPI>
__global__ __launch_bounds__(256, 2) void k_gemm(
    const float* __restrict__ A,
    const __half* __restrict__ Wh, const __half* __restrict__ Wl,
    const float* __restrict__ bias, const float* __restrict__ prelu_a,
    float* __restrict__ Cf, __half* __restrict__ Ch, int M, int K) {
    extern __shared__ char smem_raw[];
    __half* Af = (__half*)smem_raw;                  // A (single fp16)
    const int a_stride = (EPI == 1) ? AFS : SMS;
    __half* Bh = Af + 128 * a_stride;
    __half* Bl = Bh + 128 * SMS;
    __shared__ int s_off[129];

    const int tid = threadIdx.x;
    const int lane = tid & 31;
    const int wid = tid >> 5;
    const int g = lane >> 2;
    const int t = lane & 3;
    const int warp_m = wid & 3;
    const int warp_n = wid >> 2;
    const int row0 = blockIdx.x * 128;

    const int ld_row = tid >> 1;
    const int ld_k = (tid & 1) * 16;

    // ---------------- EPI==1 prologue: CSR gather-mean into smem ----------------
    if (EPI == 1) {
        for (int i = tid; i < 129; i += 256)
            s_off[i] = g_off[min(row0 + i, M)];
        __syncthreads();
        const int base = s_off[0];
        const int total = s_off[128] - base;
        int* s_idx = (int*)Bh;  // Bh+Bl contiguous: 20KB = 5120 ints
        const int n_sm = min(total, ICAP);
        for (int i = tid; i < n_sm; i += 256)
            s_idx[i] = g_csr[base + i];
        __syncthreads();

        const int gr = tid >> 4;
        const int gc = (tid & 15) * 8;
#pragma unroll
        for (int w = 0; w < 8; w++) {
            int r = w * 16 + gr;
            int st = s_off[r] - base;
            int en = s_off[r + 1] - base;
            float s[8];
#pragma unroll
            for (int j = 0; j < 8; j++) s[j] = 0.f;
            for (int i = st; i < en; i++) {
                int se = (i < n_sm) ? s_idx[i] : g_csr[base + i];
                float4 raw = *(const float4*)&g_fused[(size_t)se * 128 + gc];
                unsigned u0 = __float_as_uint(raw.x), u1 = __float_as_uint(raw.y);
                unsigned u2 = __float_as_uint(raw.z), u3 = __float_as_uint(raw.w);
                float2 v0 = __half22float2(*(__half2*)&u0);
                float2 v1 = __half22float2(*(__half2*)&u1);
                float2 v2 = __half22float2(*(__half2*)&u2);
                float2 v3 = __half22float2(*(__half2*)&u3);
                s[0] += v0.x; s[1] += v0.y; s[2] += v1.x; s[3] += v1.y;
                s[4] += v2.x; s[5] += v2.y; s[6] += v3.x; s[7] += v3.y;
            }
            float inv = 1.f / (float)max(en - st, 1);
            __half hv[8];
#pragma unroll
            for (int j = 0; j < 8; j++) hv[j] = __float2half_rn(s[j] * inv);
            *(uint4*)&Af[r * AFS + gc] = *(uint4*)hv;
        }
        __syncthreads();
    }

    float acc[2][8][4];
#pragma unroll
    for (int mt = 0; mt < 2; mt++)
#pragma unroll
        for (int nt = 0; nt < 8; nt++)
#pragma unroll
            for (int r = 0; r < 4; r++) acc[mt][nt][r] = 0.f;

    for (int kb = 0; kb < K; kb += 32) {
        if (EPI == 0) {
            // stage A from global fp32 -> fp16
            int r = row0 + ld_row;
            const float* src = &A[(size_t)r * K + kb + ld_k];
#pragma unroll
            for (int j = 0; j < 4; j++) {
                float4 v = make_float4(0.f, 0.f, 0.f, 0.f);
                if (r < M) v = *(const float4*)(src + j * 4);
                __half2 p0 = __floats2half2_rn(v.x, v.y);
                __half2 p1 = __floats2half2_rn(v.z, v.w);
                *(__half2*)&Af[ld_row * SMS + ld_k + j * 4] = p0;
                *(__half2*)&Af[ld_row * SMS + ld_k + j * 4 + 2] = p1;
            }
        }
        {
            // stage pre-split W: pure 16B copies
            const size_t goff = (size_t)ld_row * K + kb + ld_k;
            *(uint4*)&Bh[ld_row * SMS + ld_k] = *(const uint4*)&Wh[goff];
            *(uint4*)&Bh[ld_row * SMS + ld_k + 8] = *(const uint4*)&Wh[goff + 8];
            *(uint4*)&Bl[ld_row * SMS + ld_k] = *(const uint4*)&Wl[goff];
            *(uint4*)&Bl[ld_row * SMS + ld_k + 8] = *(const uint4*)&Wl[goff + 8];
        }
        __syncthreads();

#pragma unroll
        for (int kk = 0; kk < 32; kk += 16) {
            const int ak = (EPI == 1) ? (kb + kk) : kk;
            unsigned a[2][4];
#pragma unroll
            for (int mt = 0; mt < 2; mt++) {
                int m0 = warp_m * 32 + mt * 16 + g;
                a[mt][0] = *(const unsigned*)&Af[m0 * a_stride + ak + 2 * t];
                a[mt][1] = *(const unsigned*)&Af[(m0 + 8) * a_stride + ak + 2 * t];
                a[mt][2] = *(const unsigned*)&Af[m0 * a_stride + ak + 2 * t + 8];
                a[mt][3] = *(const unsigned*)&Af[(m0 + 8) * a_stride + ak + 2 * t + 8];
            }
#pragma unroll
            for (int nt = 0; nt < 8; nt++) {
                int n = warp_n * 64 + nt * 8 + g;
                unsigned bh0 = *(const unsigned*)&Bh[n * SMS + kk + 2 * t];
                unsigned bh1 = *(const unsigned*)&Bh[n * SMS + kk + 2 * t + 8];
                unsigned bl0 = *(const unsigned*)&Bl[n * SMS + kk + 2 * t];
                unsigned bl1 = *(const unsigned*)&Bl[n * SMS + kk + 2 * t + 8];
#pragma unroll
                for (int mt = 0; mt < 2; mt++) {
                    mma_f16(acc[mt][nt], a[mt], bh0, bh1);
                    mma_f16(acc[mt][nt], a[mt], bl0, bl1);
                }
            }
        }
        __syncthreads();
    }

    // ---------------- epilogue ----------------
    float alpha = 0.f;
    if (EPI == 1) alpha = prelu_a[0];

#pragma unroll
    for (int nt = 0; nt < 8; nt++) {
        int col = warp_n * 64 + nt * 8 + 2 * t;
        float b0 = 0.f, b1 = 0.f;
        if (EPI == 1) { b0 = bias[col]; b1 = bias[col + 1]; }
        float s0 = 0.f, s1 = 0.f, q0 = 0.f, q1 = 0.f;
#pragma unroll
        for (int mt = 0; mt < 2; mt++) {
            int r0 = row0 + warp_m * 32 + mt * 16 + g;
            int r1 = r0 + 8;
            float v0 = acc[mt][nt][0], v1 = acc[mt][nt][1];
            float v2 = acc[mt][nt][2], v3 = acc[mt][nt][3];
            if (EPI == 1) {
                v0 += b0; v1 += b1; v2 += b0; v3 += b1;
                v0 = (v0 >= 0.f) ? v0 : alpha * v0;
                v1 = (v1 >= 0.f) ? v1 : alpha * v1;
                v2 = (v2 >= 0.f) ? v2 : alpha * v2;
                v3 = (v3 >= 0.f) ? v3 : alpha * v3;
                if (r0 < M) {
                    *(__half2*)&Ch[(size_t)r0 * 128 + col] = __floats2half2_rn(v0, v1);
                    s0 += v0; s1 += v1; q0 += v0 * v0; q1 += v1 * v1;
                }
                if (r1 < M) {
                    *(__half2*)&Ch[(size_t)r1 * 128 + col] = __floats2half2_rn(v2, v3);
                    s0 += v2; s1 += v3; q0 += v2 * v2; q1 += v3 * v3;
                }
            } else {
                if (r0 < M) *(float2*)&Cf[(size_t)r0 * 128 + col] = make_float2(v0, v1);
                if (r1 < M) *(float2*)&Cf[(size_t)r1 * 128 + col] = make_float2(v2, v3);
            }
        }
        if (EPI == 1) {
#pragma unroll
            for (int m = 4; m <= 16; m <<= 1) {
                s0 += __shfl_xor_sync(0xffffffffu, s0, m);
                s1 += __shfl_xor_sync(0xffffffffu, s1, m);
                q0 += __shfl_xor_sync(0xffffffffu, q0, m);
                q1 += __shfl_xor_sync(0xffffffffu, q1, m);
            }
            if (g == 0) {
                redg_f32(&g_bnsum[col], s0);
                redg_f32(&g_bnsum[col + 1], s1);
                redg_f32(&g_bnsumsq[col], q0);
                redg_f32(&g_bnsumsq[col + 1], q1);
            }
        }
    }
}

// ====================================================================
__global__ void k_fuse(const float* __restrict__ ea, const int* __restrict__ ei,
                       int E) {
    int tt = blockIdx.x * blockDim.x + threadIdx.x;
    int e = tt >> 5;
    int lane = tt & 31;
    if (e >= E) return;
    int s = ei[e];
    int d = ei[E + e];
    if (lane == 0) atomicAdd(&g_ncnt[d], 1.f);
    int c = lane * 4;
    float4 a = *(const float4*)&ea[(size_t)e * 128 + c];
    float4 ps = *(const float4*)&g_px[(size_t)s * 128 + c];
    float4 pd = *(const float4*)&g_px[(size_t)d * 128 + c];
    __half2 h01 = __floats2half2_rn(a.x + 0.5f * (ps.x + pd.x),
                                    a.y + 0.5f * (ps.y + pd.y));
    __half2 h23 = __floats2half2_rn(a.z + 0.5f * (ps.z + pd.z),
                                    a.w + 0.5f * (ps.w + pd.w));
    float2 pk;
    pk.x = __uint_as_float(*(unsigned*)&h01);
    pk.y = __uint_as_float(*(unsigned*)&h23);
    *(float2*)&g_fused[(size_t)e * 128 + c] = pk;
}

// ---------------- CSR build ----------------
__global__ void k_lcnt(const int* __restrict__ lei, int L) {
    int tt = blockIdx.x * blockDim.x + threadIdx.x;
    if (tt < L) atomicAdd(&g_lcnt[lei[L + tt]], 1);
}

__global__ void k_scan1(int E) {
    __shared__ int s[256];
    int tid = threadIdx.x;
    int base = blockIdx.x * 1024 + tid * 4;
    int v[4], p[4];
    int tot = 0;
#pragma unroll
    for (int j = 0; j < 4; j++) {
        v[j] = (base + j < E) ? g_lcnt[base + j] : 0;
        p[j] = tot;
        tot += v[j];
    }
    s[tid] = tot;
    __syncthreads();
    for (int d = 1; d < 256; d <<= 1) {
        int tmp = (tid >= d) ? s[tid - d] : 0;
        __syncthreads();
        s[tid] += tmp;
        __syncthreads();
    }
    int excl = s[tid] - tot;
#pragma unroll
    for (int j = 0; j < 4; j++)
        if (base + j < E) g_off[base + j] = excl + p[j];
    if (tid == 255) g_bsum[blockIdx.x] = s[255];
}

__global__ void k_scan2(int nb, int E, int L) {
    __shared__ int s[1024];
    int tid = threadIdx.x;
    int v = (tid < nb) ? g_bsum[tid] : 0;
    s[tid] = v;
    __syncthreads();
    for (int d = 1; d < 1024; d <<= 1) {
        int tmp = (tid >= d) ? s[tid - d] : 0;
        __syncthreads();
        s[tid] += tmp;
        __syncthreads();
    }
    if (tid < nb) g_bsum[tid] = s[tid] - v;
    if (tid == 0) g_off[E] = L;
}

__global__ void k_scan3(int E) {
    int i = blockIdx.x * blockDim.x + threadIdx.x;
    if (i < E) g_off[i] += g_bsum[i >> 10];
}

__global__ void k_fill(const int* __restrict__ lei, int L) {
    int l = blockIdx.x * blockDim.x + threadIdx.x;
    if (l >= L) return;
    int d = lei[L + l];
    int pos = g_off[d] + atomicAdd(&g_cur[d], 1);
    g_csr[pos] = lei[l];
}

__global__ void k_bnfin(const float* __restrict__ gamma,
                        const float* __restrict__ beta, float invE) {
    int c = threadIdx.x;
    float mean = g_bnsum[c] * invE;
    float var = g_bnsumsq[c] * invE - mean * mean;
    float sc = rsqrtf(var + 1e-5f) * gamma[c];
    g_scale[c] = sc;
    g_shift[c] = beta[c] - mean * sc;
}

__global__ void k_final(const int* __restrict__ ei, float* __restrict__ out,
                        int E) {
    int tt = blockIdx.x * blockDim.x + threadIdx.x;
    int e = tt >> 5;
    int lane = tt & 31;
    if (e >= E) return;
    int d = ei[E + e];
    int c = lane * 4;
    float2 rf = *(const float2*)&g_fused[(size_t)e * 128 + c];
    float2 rh = *(const float2*)&g_h[(size_t)e * 128 + c];
    unsigned uf0 = __float_as_uint(rf.x), uf1 = __float_as_uint(rf.y);
    unsigned uh0 = __float_as_uint(rh.x), uh1 = __float_as_uint(rh.y);
    float2 f01 = __half22float2(*(__half2*)&uf0);
    float2 f23 = __half22float2(*(__half2*)&uf1);
    float2 h01 = __half22float2(*(__half2*)&uh0);
    float2 h23 = __half22float2(*(__half2*)&uh1);
    float4 sc = *(const float4*)&g_scale[c];
    float4 sh = *(const float4*)&g_shift[c];
    float4 r;
    r.x = f01.x + h01.x * sc.x + sh.x;
    r.y = f01.y + h01.y * sc.y + sh.y;
    r.z = f23.x + h23.x * sc.z + sh.z;
    r.w = f23.y + h23.y * sc.w + sh.w;
    float* p = &out[(size_t)d * 128 + c];
    asm volatile("red.global.add.v4.f32 [%0], {%1,%2,%3,%4};"
                 :: "l"(p), "f"(r.x), "f"(r.y), "f"(r.z), "f"(r.w)
                 : "memory");
}

__global__ void k_div(float* __restrict__ out, int N) {
    int tt = blockIdx.x * blockDim.x + threadIdx.x;
    int n = tt >> 5;
    int lane = tt & 31;
    if (n >= N) return;
    float inv = 1.f / fmaxf(g_ncnt[n], 1.f);
    float4* p = (float4*)&out[(size_t)n * 128 + lane * 4];
    float4 v = *p;
    v.x *= inv; v.y *= inv; v.z *= inv; v.w *= inv;
    *p = v;
}

// ====================================================================
static cudaStream_t s_aux = nullptr;
static cudaEvent_t ev_fork = nullptr, ev_join = nullptr;

extern "C" void kernel_launch(void* const* d_in, const int* in_sizes, int n_in,
                              void* d_out, int out_size) {
    const float* x     = (const float*)d_in[0];
    const float* ea    = (const float*)d_in[1];
    const float* Wp    = (const float*)d_in[2];
    const float* W1    = (const float*)d_in[3];
    const float* b1    = (const float*)d_in[4];
    const float* pa    = (const float*)d_in[5];
    const float* gamma = (const float*)d_in[6];
    const float* beta  = (const float*)d_in[7];
    const int*   ei    = (const int*)d_in[8];
    const int*   lei   = (const int*)d_in[9];

    const int N = in_sizes[0] / 256;
    const int E = in_sizes[1] / 128;
    const int L = in_sizes[9] / 2;
    float* out = (float*)d_out;

    if (!s_aux) {
        cudaStreamCreateWithFlags(&s_aux, cudaStreamNonBlocking);
        cudaEventCreateWithFlags(&ev_fork, cudaEventDisableTiming);
        cudaEventCreateWithFlags(&ev_join, cudaEventDisableTiming);
    }

    void *p_lcnt, *p_cur, *p_ncnt, *p_bns, *p_bnss, *p_px, *p_h;
    void *p_Wph, *p_Wpl, *p_W1h, *p_W1l;
    cudaGetSymbolAddress(&p_lcnt, g_lcnt);
    cudaGetSymbolAddress(&p_cur, g_cur);
    cudaGetSymbolAddress(&p_ncnt, g_ncnt);
    cudaGetSymbolAddress(&p_bns, g_bnsum);
    cudaGetSymbolAddress(&p_bnss, g_bnsumsq);
    cudaGetSymbolAddress(&p_px, g_px);
    cudaGetSymbolAddress(&p_h, g_h);
    cudaGetSymbolAddress(&p_Wph, g_Wph);
    cudaGetSymbolAddress(&p_Wpl, g_Wpl);
    cudaGetSymbolAddress(&p_W1h, g_W1h);
    cudaGetSymbolAddress(&p_W1l, g_W1l);

    cudaMemsetAsync(p_lcnt, 0, (size_t)E * sizeof(int));
    cudaMemsetAsync(p_cur, 0, (size_t)E * sizeof(int));
    cudaMemsetAsync(p_ncnt, 0, (size_t)N * sizeof(float));
    cudaMemsetAsync(p_bns, 0, 128 * sizeof(float));
    cudaMemsetAsync(p_bnss, 0, 128 * sizeof(float));
    cudaMemsetAsync(d_out, 0, (size_t)N * 128 * sizeof(float));

    const int nb = (E + 1023) / 1024;
    const int smem0 = 3 * 128 * SMS * 2;                 // A + Bh + Bl (stage)
    const int smem1 = 128 * AFS * 2 + 2 * 128 * SMS * 2; // full-K A + Bh + Bl

    cudaFuncSetAttribute(k_gemm<0>, cudaFuncAttributeMaxDynamicSharedMemorySize, smem0);
    cudaFuncSetAttribute(k_gemm<1>, cudaFuncAttributeMaxDynamicSharedMemorySize, smem1);

    k_split<<<(128 * 256 + 255) / 256, 256>>>(Wp, (__half*)p_Wph,
                                              (__half*)p_Wpl, 128 * 256);
    k_split<<<(128 * 128 + 255) / 256, 256>>>(W1, (__half*)p_W1h,
                                              (__half*)p_W1l, 128 * 128);

    // fork: CSR build on aux stream, gemm0+fuse on default
    cudaEventRecord(ev_fork, 0);
    cudaStreamWaitEvent(s_aux, ev_fork, 0);
    k_lcnt<<<(L + 255) / 256, 256, 0, s_aux>>>(lei, L);
    k_scan1<<<nb, 256, 0, s_aux>>>(E);
    k_scan2<<<1, 1024, 0, s_aux>>>(nb, E, L);
    k_scan3<<<(E + 255) / 256, 256, 0, s_aux>>>(E);
    k_fill<<<(L + 255) / 256, 256, 0, s_aux>>>(lei, L);
    cudaEventRecord(ev_join, s_aux);

    k_gemm<0><<<(N + 127) / 128, 256, smem0>>>(x, (const __half*)p_Wph,
                                               (const __half*)p_Wpl,
                                               nullptr, nullptr, (float*)p_px,
                                               nullptr, N, 256);
    k_fuse<<<(E * 32 + 255) / 256, 256>>>(ea, ei, E);

    cudaStreamWaitEvent(0, ev_join, 0);
    k_gemm<1><<<(E + 127) / 128, 256, smem1>>>(nullptr, (const __half*)p_W1h,
                                               (const __half*)p_W1l,
                                               b1, pa, nullptr, (__half*)p_h, E, 128);
    k_bnfin<<<1, 128>>>(gamma, beta, 1.f / (float)E);
    k_final<<<(E * 32 + 255) / 256, 256>>>(ei, out, E);
    k_div<<<(N * 32 + 255) / 256, 256>>>(out, N);
}